// round 7
// baseline (speedup 1.0000x reference)
#include <cuda_runtime.h>
#include <cuda_bf16.h>
#include <cstdint>
#include <math.h>

#define KD 4096
#define KI 11008
#define KM 8192

// tcgen05 is arch-specific: only present in the sm_103a compilation pass.
#if !defined(__CUDA_ARCH__) || defined(__CUDA_ARCH_FEAT_SM103_ALL)
#define TC_OK 1
#else
#define TC_OK 0
#endif

// ---------------- persistent scratch (__device__ globals; no allocs) -------
__device__ __nv_bfloat16 g_wg[(size_t)KI * KD];   // gate w bf16 [I,D]
__device__ __nv_bfloat16 g_wu[(size_t)KI * KD];   // up   w bf16 [I,D]
__device__ __nv_bfloat16 g_wd[(size_t)KD * KI];   // down w bf16 [D,I]
__device__ __nv_bfloat16 g_xh[(size_t)KM * KD];   // x hi
__device__ __nv_bfloat16 g_xl[(size_t)KM * KD];   // x lo
__device__ __nv_bfloat16 g_hh[(size_t)KM * KI];   // h hi
__device__ __nv_bfloat16 g_hl[(size_t)KM * KI];   // h lo

// ---------------- PTX helpers ----------------------------------------------
__device__ __forceinline__ uint32_t smem_u32(const void* p) {
    return (uint32_t)__cvta_generic_to_shared(p);
}
__device__ __forceinline__ void cp16(uint32_t dst, const void* src) {
    asm volatile("cp.async.cg.shared.global [%0], [%1], 16;" :: "r"(dst), "l"(src));
}
__device__ __forceinline__ void cp_commit() { asm volatile("cp.async.commit_group;"); }
__device__ __forceinline__ void cp_wait0()  { asm volatile("cp.async.wait_group 0;"); }
__device__ __forceinline__ void cp_wait1()  { asm volatile("cp.async.wait_group 1;"); }
__device__ __forceinline__ void cp_wait2()  { asm volatile("cp.async.wait_group 2;"); }

#if TC_OK
__device__ __forceinline__ bool elect1() {
    uint32_t p;
    asm volatile("{\n\t.reg .pred p;\n\telect.sync _|p, 0xFFFFFFFF;\n\t"
                 "selp.b32 %0, 1, 0, p;\n\t}" : "=r"(p));
    return p != 0;
}
__device__ __forceinline__ uint32_t ctarank() {
    uint32_t r; asm("mov.u32 %0, %%cluster_ctarank;" : "=r"(r)); return r;
}

#define TC_ALLOC2(sa, n)  asm volatile("tcgen05.alloc.cta_group::2.sync.aligned.shared::cta.b32 [%0], %1;" :: "r"(sa), "r"(n) : "memory")
#define TC_DEALLOC2(t, n) asm volatile("tcgen05.dealloc.cta_group::2.sync.aligned.b32 %0, %1;" :: "r"(t), "r"(n))
#define TC_RELINQ2()      asm volatile("tcgen05.relinquish_alloc_permit.cta_group::2.sync.aligned;")
#define TC_COMMIT_MC2(mb, mask) asm volatile("tcgen05.commit.cta_group::2.mbarrier::arrive::one.shared::cluster.multicast::cluster.b64 [%0], %1;" :: "r"(mb), "h"((uint16_t)(mask)) : "memory")
#define TC_WAIT_LD()      asm volatile("tcgen05.wait::ld.sync.aligned;" ::: "memory")
#define TC_FENCE_AFTER()  asm volatile("tcgen05.fence::after_thread_sync;" ::: "memory")
#define FENCE_ASYNC()     asm volatile("fence.proxy.async.shared::cta;" ::: "memory")
#define MBAR_INIT(a, c)   asm volatile("mbarrier.init.shared.b64 [%0], %1;" :: "r"(a), "r"(c) : "memory")
#define CLUSTER_SYNC() do { \
    asm volatile("barrier.cluster.arrive.aligned;" ::: "memory"); \
    asm volatile("barrier.cluster.wait.aligned;"   ::: "memory"); } while (0)

__device__ __forceinline__ void mbar_arrive_cluster(uint32_t addr, uint32_t rank) {
    asm volatile("{\n\t.reg .b32 ra;\n\tmapa.shared::cluster.u32 ra, %0, %1;\n\t"
                 "mbarrier.arrive.shared::cluster.b64 _, [ra];\n\t}"
                 :: "r"(addr), "r"(rank) : "memory");
}

#define MBAR_WAIT(mb, ph) do {                                                    \
    uint32_t _m = (mb), _p = (uint32_t)(ph), _d;                                  \
    asm volatile("{\n\t.reg .pred p;\n\t"                                         \
        "mbarrier.try_wait.parity.acquire.cta.shared::cta.b64 p, [%1], %2;\n\t"   \
        "selp.b32 %0, 1, 0, p;\n\t}" : "=r"(_d) : "r"(_m), "r"(_p) : "memory");   \
    if (!_d) {                                                                    \
        asm volatile("{\n\t.reg .pred P1;\n\tWL_%=:\n\t"                          \
            "mbarrier.try_wait.parity.acquire.cta.shared::cta.b64 P1, [%0], %1, 0x989680;\n\t" \
            "@P1 bra.uni WD_%=;\n\tbra.uni WL_%=;\n\tWD_%=:\n\t}"                 \
            :: "r"(_m), "r"(_p) : "memory");                                      \
    }                                                                             \
} while (0)

#define MBAR_WAIT_CL(mb, ph) do {                                                 \
    uint32_t _m = (mb), _p = (uint32_t)(ph), _d;                                  \
    asm volatile("{\n\t.reg .pred p;\n\t"                                         \
        "mbarrier.try_wait.parity.acquire.cluster.shared::cta.b64 p, [%1], %2;\n\t" \
        "selp.b32 %0, 1, 0, p;\n\t}" : "=r"(_d) : "r"(_m), "r"(_p) : "memory");   \
    if (!_d) {                                                                    \
        asm volatile("{\n\t.reg .pred P1;\n\tWL_%=:\n\t"                          \
            "mbarrier.try_wait.parity.acquire.cluster.shared::cta.b64 P1, [%0], %1, 0x989680;\n\t" \
            "@P1 bra.uni WD_%=;\n\tbra.uni WL_%=;\n\tWD_%=:\n\t}"                 \
            :: "r"(_m), "r"(_p) : "memory");                                      \
    }                                                                             \
} while (0)

#define LDTM32(r, ta)                                                             \
    asm volatile("tcgen05.ld.sync.aligned.32x32b.x32.b32 "                        \
        "{%0,%1,%2,%3,%4,%5,%6,%7,%8,%9,%10,%11,%12,%13,%14,%15,"                 \
        "%16,%17,%18,%19,%20,%21,%22,%23,%24,%25,%26,%27,%28,%29,%30,%31},[%32];" \
        : "=r"((r)[0]),"=r"((r)[1]),"=r"((r)[2]),"=r"((r)[3]),                    \
          "=r"((r)[4]),"=r"((r)[5]),"=r"((r)[6]),"=r"((r)[7]),                    \
          "=r"((r)[8]),"=r"((r)[9]),"=r"((r)[10]),"=r"((r)[11]),                  \
          "=r"((r)[12]),"=r"((r)[13]),"=r"((r)[14]),"=r"((r)[15]),                \
          "=r"((r)[16]),"=r"((r)[17]),"=r"((r)[18]),"=r"((r)[19]),                \
          "=r"((r)[20]),"=r"((r)[21]),"=r"((r)[22]),"=r"((r)[23]),                \
          "=r"((r)[24]),"=r"((r)[25]),"=r"((r)[26]),"=r"((r)[27]),                \
          "=r"((r)[28]),"=r"((r)[29]),"=r"((r)[30]),"=r"((r)[31])                 \
        : "r"(ta))

__device__ __forceinline__ uint64_t sdesc(uint32_t addr) {
    // SW128, version=1(Blackwell), SBO=64 (1024B row-group), LBO=1 (16B)
    return 0x4000404000010000ULL | (uint64_t)((addr >> 4) & 0x3FFF);
}

__device__ __forceinline__ void mma2(uint32_t d, uint64_t a, uint64_t b,
                                     uint32_t idesc, bool acc) {
    uint32_t en = acc ? 1u : 0u;
    asm volatile("{\n\t.reg .pred p;\n\tsetp.ne.u32 p, %5, 0;\n\t"
        "tcgen05.mma.cta_group::2.kind::f16 [%0], %1, %2, %3, "
        "{%4,%4,%4,%4,%4,%4,%4,%4}, p;\n\t}"
        :: "r"(d), "l"(a), "l"(b), "r"(idesc), "r"(0u), "r"(en) : "memory");
}

// idesc: F32 accum, BF16 a/b, N=256, M=256 (cg2 pair)
#define IDESC2 ((1u << 4) | (1u << 7) | (1u << 10) | ((256u / 8) << 17) | ((256u / 16) << 24))
#endif // TC_OK

// ---------------- pre-pass kernels ------------------------------------------
__global__ void __launch_bounds__(256) wconv(const int* __restrict__ w, int sel, long n4) {
    __nv_bfloat16* o = (sel == 0) ? g_wg : (sel == 1) ? g_wu : g_wd;
    long i = blockIdx.x * (long)blockDim.x + threadIdx.x;
    long stride = (long)gridDim.x * blockDim.x;
    for (; i < n4; i += stride) {
        int4 v = ((const int4*)w)[i];
        __nv_bfloat162 p0, p1;
        p0.x = __float2bfloat16((float)v.x); p0.y = __float2bfloat16((float)v.y);
        p1.x = __float2bfloat16((float)v.z); p1.y = __float2bfloat16((float)v.w);
        ((__nv_bfloat162*)o)[2 * i]     = p0;
        ((__nv_bfloat162*)o)[2 * i + 1] = p1;
    }
}

__global__ void __launch_bounds__(256) xsplit(const float* __restrict__ x, long n4) {
    long i = blockIdx.x * (long)blockDim.x + threadIdx.x;
    long stride = (long)gridDim.x * blockDim.x;
    for (; i < n4; i += stride) {
        float4 v = ((const float4*)x)[i];
        __nv_bfloat162 h0, h1, l0, l1;
        h0.x = __float2bfloat16(v.x); l0.x = __float2bfloat16(v.x - __bfloat162float(h0.x));
        h0.y = __float2bfloat16(v.y); l0.y = __float2bfloat16(v.y - __bfloat162float(h0.y));
        h1.x = __float2bfloat16(v.z); l1.x = __float2bfloat16(v.z - __bfloat162float(h1.x));
        h1.y = __float2bfloat16(v.w); l1.y = __float2bfloat16(v.w - __bfloat162float(h1.y));
        ((__nv_bfloat162*)g_xh)[2 * i] = h0; ((__nv_bfloat162*)g_xh)[2 * i + 1] = h1;
        ((__nv_bfloat162*)g_xl)[2 * i] = l0; ((__nv_bfloat162*)g_xl)[2 * i + 1] = l1;
    }
}

// ---------------- GEMM kernels: cg2 pair = M 256, 3-stage pipeline ----------
#define SST      65536
#define NSTG     3
#define GSMEM    (NSTG * SST + 1024)

#define K1_NC   (KD / 64)                // 64 chunks
#define K2_NC   (KI / 64)                // 172 chunks

// tile-order swizzle: m-pairs fastest within bands of GM, n next, bands last.
// wave of ~74 concurrent pairs then spans GM m-pairs x (74/GM) n-tiles -> both
// operands stay L2-resident instead of sweeping all n-tiles at once.
#define K1_NT   (KI / 256)               // 43 n-tiles
#define K1_MP   (KM / 256)               // 32 m-pairs
#define K1_GM   16
#define K2_NT   (KD / 512)               // 8 n-tiles
#define K2_MP   (KM / 256)               // 32 m-pairs
#define K2_GM   8

extern __shared__ char dsm[];

#if TC_OK
template <int NC, class IssueF, class MmaF>
__device__ __forceinline__ void cg2_mainloop(
    uint32_t rank, int t, int wid,
    uint32_t mb_done0, uint32_t mb_rdy0,
    IssueF issueFn, MmaF mmaFn)
{
    uint32_t phd = 0, phr = 0;
    issueFn(0, 0); cp_commit();
    issueFn(1, 1); cp_commit();
    for (int c = 0; c < NC; ++c) {
        const int s = c % 3;
        if (c + 2 < NC) {
            const int ns = (c + 2) % 3;
            if (c >= 1) {
                MBAR_WAIT(mb_done0 + ns * 8, (phd >> ns) & 1);
                phd ^= 1u << ns;
            }
            issueFn(c + 2, ns); cp_commit();
            cp_wait2();
        } else if (c + 1 < NC) {
            cp_wait1();
        } else {
            cp_wait0();
        }
        __syncthreads();
        if (t == 0) {
            FENCE_ASYNC();
            mbar_arrive_cluster(mb_rdy0 + s * 8, 0);
        }
        if (rank == 0 && wid == 0) {
            MBAR_WAIT_CL(mb_rdy0 + s * 8, (phr >> s) & 1);
            phr ^= 1u << s;
            if (elect1()) {
                mmaFn(c, s);
                TC_COMMIT_MC2(mb_done0 + s * 8, 0x3);
            }
        }
    }
    const int ls = (NC - 1) % 3;
    MBAR_WAIT(mb_done0 + ls * 8, (phd >> ls) & 1);
    TC_FENCE_AFTER();
}
#endif

// ---------------- K1: fused gate+up, M=256 pair x N=256 ----------------------
__global__ void __launch_bounds__(256, 1) __cluster_dims__(2, 1, 1)
k1(const float* __restrict__ gs_p, const float* __restrict__ us_p)
{
    // supertile decode (shared by both arch paths)
    const int idx  = blockIdx.y;
    const int band = idx / (K1_NT * K1_GM);
    const int rsub = idx % (K1_NT * K1_GM);
    const int n_t  = rsub / K1_GM;
    const int mp   = band * K1_GM + rsub % K1_GM;
    const int n0   = n_t * 256;
#if TC_OK
    const int t = threadIdx.x, wid = t >> 5, lane = t & 31;
    const uint32_t rank = ctarank();
    const int m0 = (mp * 2 + (int)rank) * 128;
    const uint32_t sb = (smem_u32(dsm) + 1023u) & ~1023u;

    __shared__ uint32_t s_tm[1];
    __shared__ alignas(8) uint64_t s_mb[6];   // done[3], rdy[3]

    if (wid == 0) TC_ALLOC2(smem_u32(s_tm), 512);
    if (t == 0) {
#pragma unroll
        for (int i = 0; i < 3; ++i) {
            MBAR_INIT(smem_u32(&s_mb[i]), 1);
            MBAR_INIT(smem_u32(&s_mb[3 + i]), 2);
        }
    }
    __syncthreads();
    CLUSTER_SYNC();
    uint32_t tm;
    asm volatile("ld.shared.b32 %0, [%1];" : "=r"(tm) : "r"(smem_u32(s_tm)));

    const int c16 = t & 7;
    const int r0  = t >> 3;
    const uint32_t swc = (uint32_t)((c16 ^ (r0 & 7)) * 16);
    const __nv_bfloat16* pxh = g_xh + (size_t)(m0 + r0) * KD + c16 * 8;
    const __nv_bfloat16* pxl = g_xl + (size_t)(m0 + r0) * KD + c16 * 8;
    const __nv_bfloat16* pbg = g_wg + (size_t)(n0 + rank * 128 + r0) * KD + c16 * 8;
    const __nv_bfloat16* pbu = g_wu + (size_t)(n0 + rank * 128 + r0) * KD + c16 * 8;

    auto issueFn = [&](int c, int s) {
        const int k0 = c * 64;
        const uint32_t st = sb + s * SST;
#pragma unroll
        for (int i = 0; i < 4; ++i) {
            const uint32_t d = (uint32_t)((r0 + 32 * i) * 128) + swc;
            cp16(st + d,         pxh + (size_t)(32 * i) * KD + k0);
            cp16(st + 16384 + d, pxl + (size_t)(32 * i) * KD + k0);
            cp16(st + 32768 + d, pbg + (size_t)(32 * i) * KD + k0);
            cp16(st + 49152 + d, pbu + (size_t)(32 * i) * KD + k0);
        }
    };
    auto mmaFn = [&](int c, int s) {
        const uint32_t st = sb + s * SST;
        const uint64_t da = sdesc(st), dl = sdesc(st + 16384);
        const uint64_t dg = sdesc(st + 32768), du = sdesc(st + 49152);
#pragma unroll
        for (int k = 0; k < 4; ++k) {
            const bool acc = (c > 0) || (k > 0);
            mma2(tm,       da + 2 * k, dg + 2 * k, IDESC2, acc);
            mma2(tm + 256, da + 2 * k, du + 2 * k, IDESC2, acc);
        }
#pragma unroll
        for (int k = 0; k < 4; ++k) {
            mma2(tm,       dl + 2 * k, dg + 2 * k, IDESC2, true);
            mma2(tm + 256, dl + 2 * k, du + 2 * k, IDESC2, true);
        }
    };

    cg2_mainloop<K1_NC>(rank, t, wid, smem_u32(&s_mb[0]), smem_u32(&s_mb[3]),
                        issueFn, mmaFn);

    const float gsc = gs_p[0], usc = us_p[0];
    const int m = m0 + (wid & 3) * 32 + lane;
    const int cb0 = (wid >> 2) * 4;
#pragma unroll 1
    for (int cb = cb0; cb < cb0 + 4; ++cb) {
        uint32_t rg[32], ru[32];
        LDTM32(rg, tm + cb * 32);
        LDTM32(ru, tm + 256 + cb * 32);
        TC_WAIT_LD();
        alignas(16) ushort oh[32], ol[32];
#pragma unroll
        for (int j = 0; j < 32; ++j) {
            const float g = __uint_as_float(rg[j]) * gsc;
            const float u = __uint_as_float(ru[j]) * usc;
            const float v = (g / (1.0f + __expf(-g))) * u;
            const __nv_bfloat16 hh = __float2bfloat16(v);
            const __nv_bfloat16 hl = __float2bfloat16(v - __bfloat162float(hh));
            oh[j] = *(const ushort*)&hh;
            ol[j] = *(const ushort*)&hl;
        }
        const size_t off = ((size_t)m * KI + n0 + cb * 32) * 2;
#pragma unroll
        for (int q = 0; q < 4; ++q) {
            *(uint4*)((char*)g_hh + off + q * 16) = *(uint4*)&oh[q * 8];
            *(uint4*)((char*)g_hl + off + q * 16) = *(uint4*)&ol[q * 8];
        }
    }
    __syncthreads();
    if (wid == 0) { TC_RELINQ2(); TC_DEALLOC2(tm, 512); }
    CLUSTER_SYNC();

#else  // SIMT fallback (never runs on GB300)
    const int t = threadIdx.x;
    const int m0 = (mp * 2 + blockIdx.x) * 128;
    float* sA = (float*)dsm;
    float* sB = (float*)(dsm + 32 * 132 * 4);
    const float gsc = gs_p[0], usc = us_p[0];
    const int tx = t & 7, ty = (t >> 3) & 15;
    for (int ns = 0; ns < 4; ++ns) {
        const int nb = n0 + ns * 64;
        float ag[8][8], au[8][8];
#pragma unroll
        for (int i = 0; i < 8; ++i)
#pragma unroll
            for (int j = 0; j < 8; ++j) { ag[i][j] = 0.f; au[i][j] = 0.f; }
        for (int pass = 0; pass < 2; ++pass) {
            const __nv_bfloat16* W = pass ? g_wu : g_wg;
            float (*acc)[8] = pass ? au : ag;
            for (int k0 = 0; k0 < KD; k0 += 32) {
                for (int i = t; i < 128 * 32; i += blockDim.x) {
                    int r = i >> 5, c = i & 31;
                    sA[c * 132 + r] = __bfloat162float(g_xh[(size_t)(m0 + r) * KD + k0 + c])
                                    + __bfloat162float(g_xl[(size_t)(m0 + r) * KD + k0 + c]);
                }
                for (int i = t; i < 64 * 32; i += blockDim.x) {
                    int r = i >> 5, c = i & 31;
                    sB[c * 68 + r] = __bfloat162float(W[(size_t)(nb + r) * KD + k0 + c]);
                }
                __syncthreads();
                for (int k = 0; k < 32; ++k) {
                    float a[8], w[8];
#pragma unroll
                    for (int i = 0; i < 8; ++i) a[i] = sA[k * 132 + ty * 8 + i];
#pragma unroll
                    for (int j = 0; j < 8; ++j) w[j] = sB[k * 68 + tx * 8 + j];
#pragma unroll
                    for (int i = 0; i < 8; ++i)
#pragma unroll
                        for (int j = 0; j < 8; ++j)
                            acc[i][j] = fmaf(a[i], w[j], acc[i][j]);
                }
                __syncthreads();
            }
        }
#pragma unroll
        for (int i = 0; i < 8; ++i)
#pragma unroll
            for (int j = 0; j < 8; ++j) {
                const float g = ag[i][j] * gsc;
                const float v = (g / (1.0f + __expf(-g))) * (au[i][j] * usc);
                const __nv_bfloat16 hh = __float2bfloat16(v);
                const __nv_bfloat16 hl = __float2bfloat16(v - __bfloat162float(hh));
                const size_t o = (size_t)(m0 + ty * 8 + i) * KI + nb + tx * 8 + j;
                g_hh[o] = hh; g_hl[o] = hl;
            }
        __syncthreads();
    }
#endif
}

// ---------------- K2: down GEMM, M=256 pair x N=512 --------------------------
__global__ void __launch_bounds__(256, 1) __cluster_dims__(2, 1, 1)
k2(const float* __restrict__ ds_p, float* __restrict__ out)
{
    const int idx  = blockIdx.y;
    const int band = idx / (K2_NT * K2_GM);
    const int rsub = idx % (K2_NT * K2_GM);
    const int n_t  = rsub / K2_GM;
    const int mp   = band * K2_GM + rsub % K2_GM;
    const int n0   = n_t * 512;
#if TC_OK
    const int t = threadIdx.x, wid = t >> 5, lane = t & 31;
    const uint32_t rank = ctarank();
    const int m0 = (mp * 2 + (int)rank) * 128;
    const uint32_t sb = (smem_u32(dsm) + 1023u) & ~1023u;

    __shared__ uint32_t s_tm[1];
    __shared__ alignas(8) uint64_t s_mb[6];

    if (wid == 0) TC_ALLOC2(smem_u32(s_tm), 512);
    if (t == 0) {
#pragma unroll
        for (int i = 0; i < 3; ++i) {
            MBAR_INIT(smem_u32(&s_mb[i]), 1);
            MBAR_INIT(smem_u32(&s_mb[3 + i]), 2);
        }
    }
    __syncthreads();
    CLUSTER_SYNC();
    uint32_t tm;
    asm volatile("ld.shared.b32 %0, [%1];" : "=r"(tm) : "r"(smem_u32(s_tm)));

    const int c16 = t & 7;
    const int r0  = t >> 3;
    const uint32_t swc = (uint32_t)((c16 ^ (r0 & 7)) * 16);
    const __nv_bfloat16* pah = g_hh + (size_t)(m0 + r0) * KI + c16 * 8;
    const __nv_bfloat16* pal = g_hl + (size_t)(m0 + r0) * KI + c16 * 8;
    const __nv_bfloat16* pb0 = g_wd + (size_t)(n0 +       rank * 128 + r0) * KI + c16 * 8;
    const __nv_bfloat16* pb1 = g_wd + (size_t)(n0 + 256 + rank * 128 + r0) * KI + c16 * 8;

    auto issueFn = [&](int c, int s) {
        const int k0 = c * 64;
        const uint32_t st = sb + s * SST;
#pragma unroll
        for (int i = 0; i < 4; ++i) {
            const uint32_t d = (uint32_t)((r0 + 32 * i) * 128) + swc;
            cp16(st + d,         pah + (size_t)(32 * i) * KI + k0);
            cp16(st + 16384 + d, pal + (size_t)(32 * i) * KI + k0);
            cp16(st + 32768 + d, pb0 + (size_t)(32 * i) * KI + k0);
            cp16(st + 49152 + d, pb1 + (size_t)(32 * i) * KI + k0);
        }
    };
    auto mmaFn = [&](int c, int s) {
        const uint32_t st = sb + s * SST;
        const uint64_t da = sdesc(st), dl = sdesc(st + 16384);
        const uint64_t d0 = sdesc(st + 32768), d1 = sdesc(st + 49152);
#pragma unroll
        for (int k = 0; k < 4; ++k) {
            const bool acc = (c > 0) || (k > 0);
            mma2(tm,       da + 2 * k, d0 + 2 * k, IDESC2, acc);
            mma2(tm + 256, da + 2 * k, d1 + 2 * k, IDESC2, acc);
        }
#pragma unroll
        for (int k = 0; k < 4; ++k) {
            mma2(tm,       dl + 2 * k, d0 + 2 * k, IDESC2, true);
            mma2(tm + 256, dl + 2 * k, d1 + 2 * k, IDESC2, true);
        }
    };

    cg2_mainloop<K2_NC>(rank, t, wid, smem_u32(&s_mb[0]), smem_u32(&s_mb[3]),
                        issueFn, mmaFn);

    const float dsc = ds_p[0];
    const int m = m0 + (wid & 3) * 32 + lane;
    const int cb0 = (wid >> 2) * 8;
#pragma unroll 1
    for (int cb = cb0; cb < cb0 + 8; ++cb) {
        uint32_t r[32];
        LDTM32(r, tm + cb * 32);
        TC_WAIT_LD();
        float* p = out + (size_t)m * KD + n0 + cb * 32;
#pragma unroll
        for (int q = 0; q < 8; ++q) {
            float4 v;
            v.x = __uint_as_float(r[q * 4 + 0]) * dsc;
            v.y = __uint_as_float(r[q * 4 + 1]) * dsc;
            v.z = __uint_as_float(r[q * 4 + 2]) * dsc;
            v.w = __uint_as_float(r[q * 4 + 3]) * dsc;
            *(float4*)(p + q * 4) = v;
        }
    }
    __syncthreads();
    if (wid == 0) { TC_RELINQ2(); TC_DEALLOC2(tm, 512); }
    CLUSTER_SYNC();

#else  // SIMT fallback
    const int t = threadIdx.x;
    const int m0 = (mp * 2 + blockIdx.x) * 128;
    float* sA = (float*)dsm;
    float* sB = (float*)(dsm + 32 * 132 * 4);
    const float dsc = ds_p[0];
    const int tx = t & 7, ty = (t >> 3) & 15;
    for (int ns = 0; ns < 8; ++ns) {
        const int nb = n0 + ns * 64;
        float acc[8][8];
#pragma unroll
        for (int i = 0; i < 8; ++i)
#pragma unroll
            for (int j = 0; j < 8; ++j) acc[i][j] = 0.f;
        for (int k0 = 0; k0 < KI; k0 += 32) {
            for (int i = t; i < 128 * 32; i += blockDim.x) {
                int r = i >> 5, c = i & 31;
                sA[c * 132 + r] = __bfloat162float(g_hh[(size_t)(m0 + r) * KI + k0 + c])
                                + __bfloat162float(g_hl[(size_t)(m0 + r) * KI + k0 + c]);
            }
            for (int i = t; i < 64 * 32; i += blockDim.x) {
                int r = i >> 5, c = i & 31;
                sB[c * 68 + r] = __bfloat162float(g_wd[(size_t)(nb + r) * KI + k0 + c]);
            }
            __syncthreads();
            for (int k = 0; k < 32; ++k) {
                float a[8], w[8];
#pragma unroll
                for (int i = 0; i < 8; ++i) a[i] = sA[k * 132 + ty * 8 + i];
#pragma unroll
                for (int j = 0; j < 8; ++j) w[j] = sB[k * 68 + tx * 8 + j];
#pragma unroll
                for (int i = 0; i < 8; ++i)
#pragma unroll
                    for (int j = 0; j < 8; ++j)
                        acc[i][j] = fmaf(a[i], w[j], acc[i][j]);
            }
            __syncthreads();
        }
#pragma unroll
        for (int i = 0; i < 8; ++i)
#pragma unroll
            for (int j = 0; j < 8; ++j)
                out[(size_t)(m0 + ty * 8 + i) * KD + nb + tx * 8 + j] = acc[i][j] * dsc;
        __syncthreads();
    }
#endif
}

// ---------------- launch ------------------------------------------------------
extern "C" void kernel_launch(void* const* d_in, const int* in_sizes, int n_in,
                              void* d_out, int out_size)
{
    const float* x  = (const float*)d_in[0];
    const int*   gw = (const int*)  d_in[1];
    const float* gs = (const float*)d_in[2];
    const int*   uw = (const int*)  d_in[3];
    const float* us = (const float*)d_in[4];
    const int*   dw = (const int*)  d_in[5];
    const float* ds = (const float*)d_in[6];
    float* out = (float*)d_out;

    cudaFuncSetAttribute(k1, cudaFuncAttributeMaxDynamicSharedMemorySize, GSMEM);
    cudaFuncSetAttribute(k2, cudaFuncAttributeMaxDynamicSharedMemorySize, GSMEM);

    const long nw4 = (long)KI * KD / 4;
    wconv<<<4096, 256>>>(gw, 0, nw4);
    wconv<<<4096, 256>>>(uw, 1, nw4);
    wconv<<<4096, 256>>>(dw, 2, nw4);
    xsplit<<<4096, 256>>>(x, (long)KM * KD / 4);

    // cluster (2,1,1) along x; y = swizzled (n, m-pair) supertile index
    k1<<<dim3(2, K1_NT * K1_MP, 1), 256, GSMEM>>>(gs, us);
    k2<<<dim3(2, K2_NT * K2_MP, 1), 256, GSMEM>>>(ds, out);
}

// round 8
// speedup vs baseline: 1.2889x; 1.2889x over previous
#include <cuda_runtime.h>
#include <cuda_bf16.h>
#include <cstdint>
#include <math.h>

#define KD 4096
#define KI 11008
#define KM 8192

// tcgen05 is arch-specific: only present in the sm_103a compilation pass.
#if !defined(__CUDA_ARCH__) || defined(__CUDA_ARCH_FEAT_SM103_ALL)
#define TC_OK 1
#else
#define TC_OK 0
#endif

// ---------------- persistent scratch (__device__ globals; no allocs) -------
__device__ __nv_bfloat16 g_wg[(size_t)KI * KD];   // gate w bf16 [I,D]
__device__ __nv_bfloat16 g_wu[(size_t)KI * KD];   // up   w bf16 [I,D]
__device__ __nv_bfloat16 g_wd[(size_t)KD * KI];   // down w bf16 [D,I]
__device__ __nv_bfloat16 g_xh[(size_t)KM * KD];   // x hi
__device__ __nv_bfloat16 g_xl[(size_t)KM * KD];   // x lo
__device__ __nv_bfloat16 g_hh[(size_t)KM * KI];   // h hi
__device__ __nv_bfloat16 g_hl[(size_t)KM * KI];   // h lo

// ---------------- PTX helpers ----------------------------------------------
__device__ __forceinline__ uint32_t smem_u32(const void* p) {
    return (uint32_t)__cvta_generic_to_shared(p);
}
__device__ __forceinline__ void cp16(uint32_t dst, const void* src) {
    asm volatile("cp.async.cg.shared.global [%0], [%1], 16;" :: "r"(dst), "l"(src));
}

#if TC_OK
__device__ __forceinline__ uint32_t ctarank() {
    uint32_t r; asm("mov.u32 %0, %%cluster_ctarank;" : "=r"(r)); return r;
}

// async arrive on mbar when all of THIS thread's prior cp.asyncs complete
#define CP_MBAR_ARRIVE(mb) \
    asm volatile("cp.async.mbarrier.arrive.noinc.shared::cta.b64 [%0];" :: "r"(mb) : "memory")

#define TC_ALLOC2(sa, n)  asm volatile("tcgen05.alloc.cta_group::2.sync.aligned.shared::cta.b32 [%0], %1;" :: "r"(sa), "r"(n) : "memory")
#define TC_DEALLOC2(t, n) asm volatile("tcgen05.dealloc.cta_group::2.sync.aligned.b32 %0, %1;" :: "r"(t), "r"(n))
#define TC_RELINQ2()      asm volatile("tcgen05.relinquish_alloc_permit.cta_group::2.sync.aligned;")
#define TC_COMMIT_MC2(mb, mask) asm volatile("tcgen05.commit.cta_group::2.mbarrier::arrive::one.shared::cluster.multicast::cluster.b64 [%0], %1;" :: "r"(mb), "h"((uint16_t)(mask)) : "memory")
#define TC_WAIT_LD()      asm volatile("tcgen05.wait::ld.sync.aligned;" ::: "memory")
#define TC_FENCE_AFTER()  asm volatile("tcgen05.fence::after_thread_sync;" ::: "memory")
#define FENCE_ASYNC()     asm volatile("fence.proxy.async.shared::cta;" ::: "memory")
#define MBAR_INIT(a, c)   asm volatile("mbarrier.init.shared.b64 [%0], %1;" :: "r"(a), "r"(c) : "memory")
#define CLUSTER_SYNC() do { \
    asm volatile("barrier.cluster.arrive.aligned;" ::: "memory"); \
    asm volatile("barrier.cluster.wait.aligned;"   ::: "memory"); } while (0)

__device__ __forceinline__ void mbar_arrive_cluster(uint32_t addr, uint32_t rank) {
    asm volatile("{\n\t.reg .b32 ra;\n\tmapa.shared::cluster.u32 ra, %0, %1;\n\t"
                 "mbarrier.arrive.shared::cluster.b64 _, [ra];\n\t}"
                 :: "r"(addr), "r"(rank) : "memory");
}

#define MBAR_WAIT(mb, ph) do {                                                    \
    uint32_t _m = (mb), _p = (uint32_t)(ph), _d;                                  \
    asm volatile("{\n\t.reg .pred p;\n\t"                                         \
        "mbarrier.try_wait.parity.acquire.cta.shared::cta.b64 p, [%1], %2;\n\t"   \
        "selp.b32 %0, 1, 0, p;\n\t}" : "=r"(_d) : "r"(_m), "r"(_p) : "memory");   \
    if (!_d) {                                                                    \
        asm volatile("{\n\t.reg .pred P1;\n\tWL_%=:\n\t"                          \
            "mbarrier.try_wait.parity.acquire.cta.shared::cta.b64 P1, [%0], %1, 0x989680;\n\t" \
            "@P1 bra.uni WD_%=;\n\tbra.uni WL_%=;\n\tWD_%=:\n\t}"                 \
            :: "r"(_m), "r"(_p) : "memory");                                      \
    }                                                                             \
} while (0)

#define MBAR_WAIT_CL(mb, ph) do {                                                 \
    uint32_t _m = (mb), _p = (uint32_t)(ph), _d;                                  \
    asm volatile("{\n\t.reg .pred p;\n\t"                                         \
        "mbarrier.try_wait.parity.acquire.cluster.shared::cta.b64 p, [%1], %2;\n\t" \
        "selp.b32 %0, 1, 0, p;\n\t}" : "=r"(_d) : "r"(_m), "r"(_p) : "memory");   \
    if (!_d) {                                                                    \
        asm volatile("{\n\t.reg .pred P1;\n\tWL_%=:\n\t"                          \
            "mbarrier.try_wait.parity.acquire.cluster.shared::cta.b64 P1, [%0], %1, 0x989680;\n\t" \
            "@P1 bra.uni WD_%=;\n\tbra.uni WL_%=;\n\tWD_%=:\n\t}"                 \
            :: "r"(_m), "r"(_p) : "memory");                                      \
    }                                                                             \
} while (0)

#define LDTM32(r, ta)                                                             \
    asm volatile("tcgen05.ld.sync.aligned.32x32b.x32.b32 "                        \
        "{%0,%1,%2,%3,%4,%5,%6,%7,%8,%9,%10,%11,%12,%13,%14,%15,"                 \
        "%16,%17,%18,%19,%20,%21,%22,%23,%24,%25,%26,%27,%28,%29,%30,%31},[%32];" \
        : "=r"((r)[0]),"=r"((r)[1]),"=r"((r)[2]),"=r"((r)[3]),                    \
          "=r"((r)[4]),"=r"((r)[5]),"=r"((r)[6]),"=r"((r)[7]),                    \
          "=r"((r)[8]),"=r"((r)[9]),"=r"((r)[10]),"=r"((r)[11]),                  \
          "=r"((r)[12]),"=r"((r)[13]),"=r"((r)[14]),"=r"((r)[15]),                \
          "=r"((r)[16]),"=r"((r)[17]),"=r"((r)[18]),"=r"((r)[19]),                \
          "=r"((r)[20]),"=r"((r)[21]),"=r"((r)[22]),"=r"((r)[23]),                \
          "=r"((r)[24]),"=r"((r)[25]),"=r"((r)[26]),"=r"((r)[27]),                \
          "=r"((r)[28]),"=r"((r)[29]),"=r"((r)[30]),"=r"((r)[31])                 \
        : "r"(ta))

__device__ __forceinline__ uint64_t sdesc(uint32_t addr) {
    // SW128, version=1(Blackwell), SBO=64 (1024B row-group), LBO=1 (16B)
    return 0x4000404000010000ULL | (uint64_t)((addr >> 4) & 0x3FFF);
}

__device__ __forceinline__ void mma2(uint32_t d, uint64_t a, uint64_t b,
                                     uint32_t idesc, bool acc) {
    uint32_t en = acc ? 1u : 0u;
    asm volatile("{\n\t.reg .pred p;\n\tsetp.ne.u32 p, %5, 0;\n\t"
        "tcgen05.mma.cta_group::2.kind::f16 [%0], %1, %2, %3, "
        "{%4,%4,%4,%4,%4,%4,%4,%4}, p;\n\t}"
        :: "r"(d), "l"(a), "l"(b), "r"(idesc), "r"(0u), "r"(en) : "memory");
}

// idesc: F32 accum, BF16 a/b, N=256, M=256 (cg2 pair)
#define IDESC2 ((1u << 4) | (1u << 7) | (1u << 10) | ((256u / 8) << 17) | ((256u / 16) << 24))
#endif // TC_OK

// ---------------- pre-pass kernels ------------------------------------------
__global__ void __launch_bounds__(256) wconv(const int* __restrict__ w, int sel, long n4) {
    __nv_bfloat16* o = (sel == 0) ? g_wg : (sel == 1) ? g_wu : g_wd;
    long i = blockIdx.x * (long)blockDim.x + threadIdx.x;
    long stride = (long)gridDim.x * blockDim.x;
    for (; i < n4; i += stride) {
        int4 v = ((const int4*)w)[i];
        __nv_bfloat162 p0, p1;
        p0.x = __float2bfloat16((float)v.x); p0.y = __float2bfloat16((float)v.y);
        p1.x = __float2bfloat16((float)v.z); p1.y = __float2bfloat16((float)v.w);
        ((__nv_bfloat162*)o)[2 * i]     = p0;
        ((__nv_bfloat162*)o)[2 * i + 1] = p1;
    }
}

__global__ void __launch_bounds__(256) xsplit(const float* __restrict__ x, long n4) {
    long i = blockIdx.x * (long)blockDim.x + threadIdx.x;
    long stride = (long)gridDim.x * blockDim.x;
    for (; i < n4; i += stride) {
        float4 v = ((const float4*)x)[i];
        __nv_bfloat162 h0, h1, l0, l1;
        h0.x = __float2bfloat16(v.x); l0.x = __float2bfloat16(v.x - __bfloat162float(h0.x));
        h0.y = __float2bfloat16(v.y); l0.y = __float2bfloat16(v.y - __bfloat162float(h0.y));
        h1.x = __float2bfloat16(v.z); l1.x = __float2bfloat16(v.z - __bfloat162float(h1.x));
        h1.y = __float2bfloat16(v.w); l1.y = __float2bfloat16(v.w - __bfloat162float(h1.y));
        ((__nv_bfloat162*)g_xh)[2 * i] = h0; ((__nv_bfloat162*)g_xh)[2 * i + 1] = h1;
        ((__nv_bfloat162*)g_xl)[2 * i] = l0; ((__nv_bfloat162*)g_xl)[2 * i + 1] = l1;
    }
}

// ---------------- GEMM kernels: cg2 pair = M 256, warp-specialized ----------
#define SST      65536
#define NSTG     3
#define GSMEM    (NSTG * SST + 1024)

#define K1_NC   (KD / 64)                // 64 chunks
#define K2_NC   (KI / 64)                // 172 chunks

// tile-order swizzle (kept from R7): m-pairs fastest within bands of GM.
#define K1_NT   (KI / 256)               // 43 n-tiles
#define K1_MP   (KM / 256)               // 32 m-pairs
#define K1_GM   16
#define K2_NT   (KD / 512)               // 8 n-tiles
#define K2_MP   (KM / 256)               // 32 m-pairs
#define K2_GM   8

extern __shared__ char dsm[];

#if TC_OK
// Warp-specialized mainloop: NO per-chunk __syncthreads.
//   producers  (t>=128): done(s) -> 32x cp16 -> cp.async.mbarrier.arrive(full(s))
//   relay      (t==32):  full(s) -> fence.proxy.async -> arrive leader rdy(s)
//   MMA leader (rank0,t==0): rdy(s) -> 16x mma2 -> commit multicast -> done(s)
// Stage s, k-th use at chunk c = 3k+s; waits use parity k&1.
template <int NC, class IssueF, class MmaF>
__device__ __forceinline__ void cg2_mainloop_ws(
    uint32_t rank, int t,
    uint32_t mb_full0, uint32_t mb_rdy0, uint32_t mb_done0,
    IssueF issueFn, MmaF mmaFn)
{
    if (t >= 128) {                       // producers
        for (int c = 0; c < NC; ++c) {
            const int s = c % 3;
            if (c >= 3) MBAR_WAIT(mb_done0 + s * 8, ((c / 3 - 1) & 1));
            issueFn(c, s);
            CP_MBAR_ARRIVE(mb_full0 + s * 8);
        }
        const int ls = (NC - 1) % 3, kl = (NC - 1) / 3;
        MBAR_WAIT(mb_done0 + ls * 8, kl & 1);   // absorb final MMA completion
    } else if (t == 32) {                 // relay
        for (int c = 0; c < NC; ++c) {
            const int s = c % 3;
            MBAR_WAIT(mb_full0 + s * 8, (c / 3) & 1);
            FENCE_ASYNC();
            mbar_arrive_cluster(mb_rdy0 + s * 8, 0);
        }
    } else if (rank == 0 && t == 0) {     // MMA leader
        for (int c = 0; c < NC; ++c) {
            const int s = c % 3;
            MBAR_WAIT_CL(mb_rdy0 + s * 8, (c / 3) & 1);
            mmaFn(c, s);
            TC_COMMIT_MC2(mb_done0 + s * 8, 0x3);
        }
    }
    __syncthreads();                       // producers gate everyone on final done
    TC_FENCE_AFTER();
}
#endif

// ---------------- K1: fused gate+up, M=256 pair x N=256 ----------------------
__global__ void __launch_bounds__(256, 1) __cluster_dims__(2, 1, 1)
k1(const float* __restrict__ gs_p, const float* __restrict__ us_p)
{
    const int idx  = blockIdx.y;
    const int band = idx / (K1_NT * K1_GM);
    const int rsub = idx % (K1_NT * K1_GM);
    const int n_t  = rsub / K1_GM;
    const int mp   = band * K1_GM + rsub % K1_GM;
    const int n0   = n_t * 256;
#if TC_OK
    const int t = threadIdx.x, wid = t >> 5, lane = t & 31;
    const uint32_t rank = ctarank();
    const int m0 = (mp * 2 + (int)rank) * 128;
    const uint32_t sb = (smem_u32(dsm) + 1023u) & ~1023u;

    __shared__ uint32_t s_tm[1];
    __shared__ alignas(8) uint64_t s_mb[9];   // full[3], rdy[3], done[3]

    if (wid == 0) TC_ALLOC2(smem_u32(s_tm), 512);
    if (t == 0) {
#pragma unroll
        for (int i = 0; i < 3; ++i) {
            MBAR_INIT(smem_u32(&s_mb[i]),     128);   // full: 128 producer arrives
            MBAR_INIT(smem_u32(&s_mb[3 + i]), 2);     // rdy: relay arrive x2 CTAs
            MBAR_INIT(smem_u32(&s_mb[6 + i]), 1);     // done: commit multicast
        }
    }
    __syncthreads();
    CLUSTER_SYNC();
    uint32_t tm;
    asm volatile("ld.shared.b32 %0, [%1];" : "=r"(tm) : "r"(smem_u32(s_tm)));

    // producer indexing: 128 threads (t in [128,256))
    const int tp  = (t >= 128) ? (t - 128) : 0;
    const int c16 = tp & 7;
    const int r0  = tp >> 3;                          // 0..15
    const uint32_t swc = (uint32_t)((c16 ^ (r0 & 7)) * 16);
    const __nv_bfloat16* pxh = g_xh + (size_t)(m0 + r0) * KD + c16 * 8;
    const __nv_bfloat16* pxl = g_xl + (size_t)(m0 + r0) * KD + c16 * 8;
    const __nv_bfloat16* pbg = g_wg + (size_t)(n0 + rank * 128 + r0) * KD + c16 * 8;
    const __nv_bfloat16* pbu = g_wu + (size_t)(n0 + rank * 128 + r0) * KD + c16 * 8;

    auto issueFn = [&](int c, int s) {
        const int k0 = c * 64;
        const uint32_t st = sb + s * SST;
#pragma unroll
        for (int i = 0; i < 8; ++i) {                 // 16 rows/thread-stride, 8 iters
            const uint32_t d = (uint32_t)((r0 + 16 * i) * 128) + swc;
            const size_t go = (size_t)(16 * i) * KD + k0;
            cp16(st + d,         pxh + go);
            cp16(st + 16384 + d, pxl + go);
            cp16(st + 32768 + d, pbg + go);
            cp16(st + 49152 + d, pbu + go);
        }
    };
    auto mmaFn = [&](int c, int s) {
        const uint32_t st = sb + s * SST;
        const uint64_t da = sdesc(st), dl = sdesc(st + 16384);
        const uint64_t dg = sdesc(st + 32768), du = sdesc(st + 49152);
#pragma unroll
        for (int k = 0; k < 4; ++k) {
            const bool acc = (c > 0) || (k > 0);
            mma2(tm,       da + 2 * k, dg + 2 * k, IDESC2, acc);
            mma2(tm + 256, da + 2 * k, du + 2 * k, IDESC2, acc);
        }
#pragma unroll
        for (int k = 0; k < 4; ++k) {
            mma2(tm,       dl + 2 * k, dg + 2 * k, IDESC2, true);
            mma2(tm + 256, dl + 2 * k, du + 2 * k, IDESC2, true);
        }
    };

    cg2_mainloop_ws<K1_NC>(rank, t, smem_u32(&s_mb[0]), smem_u32(&s_mb[3]),
                           smem_u32(&s_mb[6]), issueFn, mmaFn);

    const float gsc = gs_p[0], usc = us_p[0];
    const int m = m0 + (wid & 3) * 32 + lane;
    const int cb0 = (wid >> 2) * 4;
#pragma unroll 1
    for (int cb = cb0; cb < cb0 + 4; ++cb) {
        uint32_t rg[32], ru[32];
        LDTM32(rg, tm + cb * 32);
        LDTM32(ru, tm + 256 + cb * 32);
        TC_WAIT_LD();
        alignas(16) ushort oh[32], ol[32];
#pragma unroll
        for (int j = 0; j < 32; ++j) {
            const float g = __uint_as_float(rg[j]) * gsc;
            const float u = __uint_as_float(ru[j]) * usc;
            const float v = (g / (1.0f + __expf(-g))) * u;
            const __nv_bfloat16 hh = __float2bfloat16(v);
            const __nv_bfloat16 hl = __float2bfloat16(v - __bfloat162float(hh));
            oh[j] = *(const ushort*)&hh;
            ol[j] = *(const ushort*)&hl;
        }
        const size_t off = ((size_t)m * KI + n0 + cb * 32) * 2;
#pragma unroll
        for (int q = 0; q < 4; ++q) {
            *(uint4*)((char*)g_hh + off + q * 16) = *(uint4*)&oh[q * 8];
            *(uint4*)((char*)g_hl + off + q * 16) = *(uint4*)&ol[q * 8];
        }
    }
    __syncthreads();
    if (wid == 0) { TC_RELINQ2(); TC_DEALLOC2(tm, 512); }
    CLUSTER_SYNC();

#else  // SIMT fallback (never runs on GB300)
    const int t = threadIdx.x;
    const int m0 = (mp * 2 + blockIdx.x) * 128;
    float* sA = (float*)dsm;
    float* sB = (float*)(dsm + 32 * 132 * 4);
    const float gsc = gs_p[0], usc = us_p[0];
    const int tx = t & 7, ty = (t >> 3) & 15;
    for (int ns = 0; ns < 4; ++ns) {
        const int nb = n0 + ns * 64;
        float ag[8][8], au[8][8];
#pragma unroll
        for (int i = 0; i < 8; ++i)
#pragma unroll
            for (int j = 0; j < 8; ++j) { ag[i][j] = 0.f; au[i][j] = 0.f; }
        for (int pass = 0; pass < 2; ++pass) {
            const __nv_bfloat16* W = pass ? g_wu : g_wg;
            float (*acc)[8] = pass ? au : ag;
            for (int k0 = 0; k0 < KD; k0 += 32) {
                for (int i = t; i < 128 * 32; i += blockDim.x) {
                    int r = i >> 5, c = i & 31;
                    sA[c * 132 + r] = __bfloat162float(g_xh[(size_t)(m0 + r) * KD + k0 + c])
                                    + __bfloat162float(g_xl[(size_t)(m0 + r) * KD + k0 + c]);
                }
                for (int i = t; i < 64 * 32; i += blockDim.x) {
                    int r = i >> 5, c = i & 31;
                    sB[c * 68 + r] = __bfloat162float(W[(size_t)(nb + r) * KD + k0 + c]);
                }
                __syncthreads();
                for (int k = 0; k < 32; ++k) {
                    float a[8], w[8];
#pragma unroll
                    for (int i = 0; i < 8; ++i) a[i] = sA[k * 132 + ty * 8 + i];
#pragma unroll
                    for (int j = 0; j < 8; ++j) w[j] = sB[k * 68 + tx * 8 + j];
#pragma unroll
                    for (int i = 0; i < 8; ++i)
#pragma unroll
                        for (int j = 0; j < 8; ++j)
                            acc[i][j] = fmaf(a[i], w[j], acc[i][j]);
                }
                __syncthreads();
            }
        }
#pragma unroll
        for (int i = 0; i < 8; ++i)
#pragma unroll
            for (int j = 0; j < 8; ++j) {
                const float g = ag[i][j] * gsc;
                const float v = (g / (1.0f + __expf(-g))) * (au[i][j] * usc);
                const __nv_bfloat16 hh = __float2bfloat16(v);
                const __nv_bfloat16 hl = __float2bfloat16(v - __bfloat162float(hh));
                const size_t o = (size_t)(m0 + ty * 8 + i) * KI + nb + tx * 8 + j;
                g_hh[o] = hh; g_hl[o] = hl;
            }
        __syncthreads();
    }
#endif
}

// ---------------- K2: down GEMM, M=256 pair x N=512 --------------------------
__global__ void __launch_bounds__(256, 1) __cluster_dims__(2, 1, 1)
k2(const float* __restrict__ ds_p, float* __restrict__ out)
{
    const int idx  = blockIdx.y;
    const int band = idx / (K2_NT * K2_GM);
    const int rsub = idx % (K2_NT * K2_GM);
    const int n_t  = rsub / K2_GM;
    const int mp   = band * K2_GM + rsub % K2_GM;
    const int n0   = n_t * 512;
#if TC_OK
    const int t = threadIdx.x, wid = t >> 5, lane = t & 31;
    const uint32_t rank = ctarank();
    const int m0 = (mp * 2 + (int)rank) * 128;
    const uint32_t sb = (smem_u32(dsm) + 1023u) & ~1023u;

    __shared__ uint32_t s_tm[1];
    __shared__ alignas(8) uint64_t s_mb[9];

    if (wid == 0) TC_ALLOC2(smem_u32(s_tm), 512);
    if (t == 0) {
#pragma unroll
        for (int i = 0; i < 3; ++i) {
            MBAR_INIT(smem_u32(&s_mb[i]),     128);
            MBAR_INIT(smem_u32(&s_mb[3 + i]), 2);
            MBAR_INIT(smem_u32(&s_mb[6 + i]), 1);
        }
    }
    __syncthreads();
    CLUSTER_SYNC();
    uint32_t tm;
    asm volatile("ld.shared.b32 %0, [%1];" : "=r"(tm) : "r"(smem_u32(s_tm)));

    const int tp  = (t >= 128) ? (t - 128) : 0;
    const int c16 = tp & 7;
    const int r0  = tp >> 3;
    const uint32_t swc = (uint32_t)((c16 ^ (r0 & 7)) * 16);
    const __nv_bfloat16* pah = g_hh + (size_t)(m0 + r0) * KI + c16 * 8;
    const __nv_bfloat16* pal = g_hl + (size_t)(m0 + r0) * KI + c16 * 8;
    const __nv_bfloat16* pb0 = g_wd + (size_t)(n0 +       rank * 128 + r0) * KI + c16 * 8;
    const __nv_bfloat16* pb1 = g_wd + (size_t)(n0 + 256 + rank * 128 + r0) * KI + c16 * 8;

    auto issueFn = [&](int c, int s) {
        const int k0 = c * 64;
        const uint32_t st = sb + s * SST;
#pragma unroll
        for (int i = 0; i < 8; ++i) {
            const uint32_t d = (uint32_t)((r0 + 16 * i) * 128) + swc;
            const size_t go = (size_t)(16 * i) * KI + k0;
            cp16(st + d,         pah + go);
            cp16(st + 16384 + d, pal + go);
            cp16(st + 32768 + d, pb0 + go);
            cp16(st + 49152 + d, pb1 + go);
        }
    };
    auto mmaFn = [&](int c, int s) {
        const uint32_t st = sb + s * SST;
        const uint64_t da = sdesc(st), dl = sdesc(st + 16384);
        const uint64_t d0 = sdesc(st + 32768), d1 = sdesc(st + 49152);
#pragma unroll
        for (int k = 0; k < 4; ++k) {
            const bool acc = (c > 0) || (k > 0);
            mma2(tm,       da + 2 * k, d0 + 2 * k, IDESC2, acc);
            mma2(tm + 256, da + 2 * k, d1 + 2 * k, IDESC2, acc);
        }
#pragma unroll
        for (int k = 0; k < 4; ++k) {
            mma2(tm,       dl + 2 * k, d0 + 2 * k, IDESC2, true);
            mma2(tm + 256, dl + 2 * k, d1 + 2 * k, IDESC2, true);
        }
    };

    cg2_mainloop_ws<K2_NC>(rank, t, smem_u32(&s_mb[0]), smem_u32(&s_mb[3]),
                           smem_u32(&s_mb[6]), issueFn, mmaFn);

    const float dsc = ds_p[0];
    const int m = m0 + (wid & 3) * 32 + lane;
    const int cb0 = (wid >> 2) * 8;
#pragma unroll 1
    for (int cb = cb0; cb < cb0 + 8; ++cb) {
        uint32_t r[32];
        LDTM32(r, tm + cb * 32);
        TC_WAIT_LD();
        float* p = out + (size_t)m * KD + n0 + cb * 32;
#pragma unroll
        for (int q = 0; q < 8; ++q) {
            float4 v;
            v.x = __uint_as_float(r[q * 4 + 0]) * dsc;
            v.y = __uint_as_float(r[q * 4 + 1]) * dsc;
            v.z = __uint_as_float(r[q * 4 + 2]) * dsc;
            v.w = __uint_as_float(r[q * 4 + 3]) * dsc;
            *(float4*)(p + q * 4) = v;
        }
    }
    __syncthreads();
    if (wid == 0) { TC_RELINQ2(); TC_DEALLOC2(tm, 512); }
    CLUSTER_SYNC();

#else  // SIMT fallback
    const int t = threadIdx.x;
    const int m0 = (mp * 2 + blockIdx.x) * 128;
    float* sA = (float*)dsm;
    float* sB = (float*)(dsm + 32 * 132 * 4);
    const float dsc = ds_p[0];
    const int tx = t & 7, ty = (t >> 3) & 15;
    for (int ns = 0; ns < 8; ++ns) {
        const int nb = n0 + ns * 64;
        float acc[8][8];
#pragma unroll
        for (int i = 0; i < 8; ++i)
#pragma unroll
            for (int j = 0; j < 8; ++j) acc[i][j] = 0.f;
        for (int k0 = 0; k0 < KI; k0 += 32) {
            for (int i = t; i < 128 * 32; i += blockDim.x) {
                int r = i >> 5, c = i & 31;
                sA[c * 132 + r] = __bfloat162float(g_hh[(size_t)(m0 + r) * KI + k0 + c])
                                + __bfloat162float(g_hl[(size_t)(m0 + r) * KI + k0 + c]);
            }
            for (int i = t; i < 64 * 32; i += blockDim.x) {
                int r = i >> 5, c = i & 31;
                sB[c * 68 + r] = __bfloat162float(g_wd[(size_t)(nb + r) * KI + k0 + c]);
            }
            __syncthreads();
            for (int k = 0; k < 32; ++k) {
                float a[8], w[8];
#pragma unroll
                for (int i = 0; i < 8; ++i) a[i] = sA[k * 132 + ty * 8 + i];
#pragma unroll
                for (int j = 0; j < 8; ++j) w[j] = sB[k * 68 + tx * 8 + j];
#pragma unroll
                for (int i = 0; i < 8; ++i)
#pragma unroll
                    for (int j = 0; j < 8; ++j)
                        acc[i][j] = fmaf(a[i], w[j], acc[i][j]);
            }
            __syncthreads();
        }
#pragma unroll
        for (int i = 0; i < 8; ++i)
#pragma unroll
            for (int j = 0; j < 8; ++j)
                out[(size_t)(m0 + ty * 8 + i) * KD + nb + tx * 8 + j] = acc[i][j] * dsc;
        __syncthreads();
    }
#endif
}

// ---------------- launch ------------------------------------------------------
extern "C" void kernel_launch(void* const* d_in, const int* in_sizes, int n_in,
                              void* d_out, int out_size)
{
    const float* x  = (const float*)d_in[0];
    const int*   gw = (const int*)  d_in[1];
    const float* gs = (const float*)d_in[2];
    const int*   uw = (const int*)  d_in[3];
    const float* us = (const float*)d_in[4];
    const int*   dw = (const int*)  d_in[5];
    const float* ds = (const float*)d_in[6];
    float* out = (float*)d_out;

    cudaFuncSetAttribute(k1, cudaFuncAttributeMaxDynamicSharedMemorySize, GSMEM);
    cudaFuncSetAttribute(k2, cudaFuncAttributeMaxDynamicSharedMemorySize, GSMEM);

    const long nw4 = (long)KI * KD / 4;
    wconv<<<4096, 256>>>(gw, 0, nw4);
    wconv<<<4096, 256>>>(uw, 1, nw4);
    wconv<<<4096, 256>>>(dw, 2, nw4);
    xsplit<<<4096, 256>>>(x, (long)KM * KD / 4);

    k1<<<dim3(2, K1_NT * K1_MP, 1), 256, GSMEM>>>(gs, us);
    k2<<<dim3(2, K2_NT * K2_MP, 1), 256, GSMEM>>>(ds, out);
}